// round 1
// baseline (speedup 1.0000x reference)
#include <cuda_runtime.h>
#include <cuda_bf16.h>

#define T_FRAMES 60
#define HID 32
#define NG 128          // 4*HID gate rows
#define EPSF 1e-5f

// scratch: per-frame input-side gate pre-activations (includes both biases)
__device__ float g_gx[T_FRAMES * NG];

__device__ __forceinline__ float sigm(float x) {
    return __fdividef(1.0f, 1.0f + __expf(-x));
}
__device__ __forceinline__ float tanh_fast(float x) {
    return __fdividef(2.0f, 1.0f + __expf(-2.0f * x)) - 1.0f;
}

// ---------------------------------------------------------------------------
// Kernel 1: one block per frame. Computes
//   f1 = relu(W00 x_t + b00)            [63]
//   f2 = relu(W01 f1 + b01)             [64]
//   fn = LayerNorm(f2) * ln_g + ln_b    [64]
//   gx = W_ih fn + b_ih + b_hh          [128]
// Fully parallel across the 60 frames (LSTM state not involved).
// ---------------------------------------------------------------------------
__global__ void frame_kernel(const float* __restrict__ x,
                             const float* __restrict__ w00, const float* __restrict__ b00,
                             const float* __restrict__ w01, const float* __restrict__ b01,
                             const float* __restrict__ lng, const float* __restrict__ lnb,
                             const float* __restrict__ wih, const float* __restrict__ bih,
                             const float* __restrict__ bhh)
{
    const int t = blockIdx.x;
    const int tid = threadIdx.x;

    __shared__ float sx[63];
    __shared__ float sf1[63];
    __shared__ float sf2[64];
    __shared__ float sfn[64];
    __shared__ float s_mu, s_rstd;

    if (tid < 63) sx[tid] = x[t * 63 + tid];
    __syncthreads();

    if (tid < 63) {
        float acc = b00[tid];
        const float* wr = w00 + tid * 63;
        #pragma unroll
        for (int k = 0; k < 63; k++) acc = fmaf(wr[k], sx[k], acc);
        sf1[tid] = fmaxf(acc, 0.0f);
    }
    __syncthreads();

    if (tid < 64) {
        float acc = b01[tid];
        const float* wr = w01 + tid * 63;
        #pragma unroll
        for (int k = 0; k < 63; k++) acc = fmaf(wr[k], sf1[k], acc);
        sf2[tid] = fmaxf(acc, 0.0f);
    }
    __syncthreads();

    // LayerNorm statistics over 64 elements, warp 0 only
    if (tid < 32) {
        float v0 = sf2[tid], v1 = sf2[tid + 32];
        float s = v0 + v1;
        float q = v0 * v0 + v1 * v1;
        #pragma unroll
        for (int o = 16; o > 0; o >>= 1) {
            s += __shfl_xor_sync(0xffffffffu, s, o);
            q += __shfl_xor_sync(0xffffffffu, q, o);
        }
        if (tid == 0) {
            float mu  = s * (1.0f / 64.0f);
            float var = q * (1.0f / 64.0f) - mu * mu;
            s_mu   = mu;
            s_rstd = rsqrtf(var + EPSF);
        }
    }
    __syncthreads();

    if (tid < 64)
        sfn[tid] = (sf2[tid] - s_mu) * s_rstd * lng[tid] + lnb[tid];
    __syncthreads();

    // gate pre-activation, one row per thread (128 rows)
    {
        float acc = bih[tid] + bhh[tid];
        const float* wr = wih + tid * 64;
        #pragma unroll
        for (int k = 0; k < 64; k++) acc = fmaf(wr[k], sfn[k], acc);
        g_gx[t * NG + tid] = acc;
    }
}

// ---------------------------------------------------------------------------
// Kernel 2: single block; warp 0 runs the entire recurrence with
// register-resident W_hh (4 rows/lane = 128 regs) and register h/c.
// Cross-lane h distribution via shuffle -> zero barriers in the loop.
// Then the output head (BN + 32->32->32->256 MLP) in the same warp.
// ---------------------------------------------------------------------------
__global__ void __launch_bounds__(128, 1) seq_kernel(
    const float* __restrict__ whh,
    const float* __restrict__ bng, const float* __restrict__ bnb,
    const float* __restrict__ w10, const float* __restrict__ b10,
    const float* __restrict__ w11, const float* __restrict__ b11,
    const float* __restrict__ w12, const float* __restrict__ b12,
    float* __restrict__ out)
{
    __shared__ float sgx[T_FRAMES * NG];       // 30 KB
    const int tid = threadIdx.x;

    // cooperative preload of gx into smem (vectorized)
    {
        float4* s4 = reinterpret_cast<float4*>(sgx);
        const float4* g4 = reinterpret_cast<const float4*>(g_gx);
        #pragma unroll
        for (int i = tid; i < (T_FRAMES * NG) / 4; i += 128) s4[i] = g4[i];
    }
    __syncthreads();
    if (tid >= 32) return;     // warps 1..3 were only for the preload

    const int lane = tid;
    const unsigned FULL = 0xffffffffu;

    // W_hh rows (lane), (lane+32), (lane+64), (lane+96) -> registers
    float wi[HID], wf[HID], wg[HID], wo[HID];
    {
        const float4* w4 = reinterpret_cast<const float4*>(whh);
        #pragma unroll
        for (int k4 = 0; k4 < HID / 4; k4++) {
            float4 a = w4[(lane       ) * (HID / 4) + k4];
            float4 b = w4[(lane + 32  ) * (HID / 4) + k4];
            float4 c = w4[(lane + 64  ) * (HID / 4) + k4];
            float4 d = w4[(lane + 96  ) * (HID / 4) + k4];
            wi[4*k4+0]=a.x; wi[4*k4+1]=a.y; wi[4*k4+2]=a.z; wi[4*k4+3]=a.w;
            wf[4*k4+0]=b.x; wf[4*k4+1]=b.y; wf[4*k4+2]=b.z; wf[4*k4+3]=b.w;
            wg[4*k4+0]=c.x; wg[4*k4+1]=c.y; wg[4*k4+2]=c.z; wg[4*k4+3]=c.w;
            wo[4*k4+0]=d.x; wo[4*k4+1]=d.y; wo[4*k4+2]=d.z; wo[4*k4+3]=d.w;
        }
    }

    float h = 0.0f, c = 0.0f;

    #pragma unroll 1
    for (int t = 0; t < T_FRAMES; t++) {
        const float* gp = sgx + t * NG;
        float gi = gp[lane];
        float gf = gp[lane + 32];
        float gg = gp[lane + 64];
        float go = gp[lane + 96];

        #pragma unroll
        for (int k = 0; k < HID; k++) {
            float hk = __shfl_sync(FULL, h, k);
            gi = fmaf(wi[k], hk, gi);
            gf = fmaf(wf[k], hk, gf);
            gg = fmaf(wg[k], hk, gg);
            go = fmaf(wo[k], hk, go);
        }

        c = sigm(gf) * c + sigm(gi) * tanh_fast(gg);
        h = sigm(go) * tanh_fast(c);
    }

    // ---- output head (warp 0, shuffles only) ----
    // BatchNorm1d eval with running_mean=0, running_var=1:
    float hb = (h * rsqrtf(1.0f + EPSF)) * bng[lane] + bnb[lane];

    float o1 = b10[lane];
    #pragma unroll
    for (int k = 0; k < 32; k++)
        o1 = fmaf(w10[lane * 32 + k], __shfl_sync(FULL, hb, k), o1);
    o1 = fmaxf(o1, 0.0f);

    float o2 = b11[lane];
    #pragma unroll
    for (int k = 0; k < 32; k++)
        o2 = fmaf(w11[lane * 32 + k], __shfl_sync(FULL, o1, k), o2);
    o2 = fmaxf(o2, 0.0f);

    float acc[8];
    #pragma unroll
    for (int m = 0; m < 8; m++) acc[m] = b12[m * 32 + lane];
    #pragma unroll
    for (int k = 0; k < 32; k++) {
        float v = __shfl_sync(FULL, o2, k);
        #pragma unroll
        for (int m = 0; m < 8; m++)
            acc[m] = fmaf(w12[(m * 32 + lane) * 32 + k], v, acc[m]);
    }
    #pragma unroll
    for (int m = 0; m < 8; m++) out[m * 32 + lane] = acc[m];
}

// ---------------------------------------------------------------------------
// Input order (metadata): x, w00, b00, w01, b01, ln_g, ln_b, w_ih, w_hh,
//                         b_ih, b_hh, bn_g, bn_b, w10, b10, w11, b11, w12, b12
// ---------------------------------------------------------------------------
extern "C" void kernel_launch(void* const* d_in, const int* in_sizes, int n_in,
                              void* d_out, int out_size)
{
    const float* x    = (const float*)d_in[0];
    const float* w00  = (const float*)d_in[1];
    const float* b00  = (const float*)d_in[2];
    const float* w01  = (const float*)d_in[3];
    const float* b01  = (const float*)d_in[4];
    const float* lng  = (const float*)d_in[5];
    const float* lnb  = (const float*)d_in[6];
    const float* wih  = (const float*)d_in[7];
    const float* whh  = (const float*)d_in[8];
    const float* bih  = (const float*)d_in[9];
    const float* bhh  = (const float*)d_in[10];
    const float* bng  = (const float*)d_in[11];
    const float* bnb  = (const float*)d_in[12];
    const float* w10  = (const float*)d_in[13];
    const float* b10  = (const float*)d_in[14];
    const float* w11  = (const float*)d_in[15];
    const float* b11  = (const float*)d_in[16];
    const float* w12  = (const float*)d_in[17];
    const float* b12  = (const float*)d_in[18];
    float* out = (float*)d_out;

    frame_kernel<<<T_FRAMES, 128>>>(x, w00, b00, w01, b01, lng, lnb, wih, bih, bhh);
    seq_kernel<<<1, 128>>>(whh, bng, bnb, w10, b10, w11, b11, w12, b12, out);
}